// round 9
// baseline (speedup 1.0000x reference)
#include <cuda_runtime.h>

#define BB 64
#define CC 512
#define TT 16
#define HWD 196
#define KK 8
#define BCHUNK 8                            // batches per chunk (51MB, 2 chunks < L2)
#define NCHUNK (BB / BCHUNK)                // 8
#define CPB_P 2                             // slabs per pool unit
#define CPB_G 2                             // slabs per gather unit
#define POOL_UNITS ((BCHUNK * CC) / CPB_P)  // 2048 (256 per batch)
#define GATH_UNITS ((BCHUNK * CC) / CPB_G)  // 2048 (256 per batch)
#define GRID_TGT 512

// [b][t][c] per-channel partial scores
__device__ float    g_partial[BB * TT * CC];
// [b][t] -> output slot (0-7 approx pos, 8-15 = 8+detail pos)
__device__ int      g_dest[BB * TT];
// per-batch pool-completion counters: exactly 256 adds per launch -> modulo-safe
__device__ unsigned g_pcnt[BB];
// work-stealing tickets (POOL_UNITS+N / GATH_UNITS+N adds per launch)
__device__ unsigned g_tkp[NCHUNK];
__device__ unsigned g_tkg[NCHUNK];
// barrier counters (N adds per launch)
__device__ unsigned g_bar[NCHUNK];

__global__ __launch_bounds__(256) void k_fused(const float* __restrict__ x,
                                               float* __restrict__ out) {
    __shared__ float    pooled[CPB_P * TT * 49];   // 1568
    __shared__ float    sc[CPB_P * 49];            // 98
    __shared__ float    v[TT];
    __shared__ int      fa[TT], fd[TT], dst_slot[TT];
    __shared__ unsigned sm_u;
    __shared__ int      sm_sel;

    const unsigned N = gridDim.x;
    const unsigned MODP = POOL_UNITS + N;
    const unsigned MODG = GATH_UNITS + N;
    const float4* __restrict__ src4 = (const float4*)x;
    float4* __restrict__ out4 = (float4*)out;

    for (int chunk = 0; chunk < NCHUNK; chunk++) {
        const int b0 = chunk * BCHUNK;

        // ============ pool phase: work-stealing, 2-slab units ============
        for (;;) {
            if (threadIdx.x == 0)
                sm_u = atomicAdd(&g_tkp[chunk], 1u) % MODP;
            __syncthreads();
            const unsigned u = sm_u;
            if (u >= POOL_UNITS) break;

            const int bc0 = b0 * CC + (int)u * CPB_P;
            const int b   = bc0 >> 9;
            const float* __restrict__ base = x + (size_t)bc0 * (TT * HWD);

            if (threadIdx.x < CPB_P * TT * 7) {        // 224 strips
                int s  = threadIdx.x;
                int ch = s / 112;
                int q  = s - ch * 112;
                int t  = q / 7;
                int y  = q - t * 7;                    // pool row (rows 2y,2y+1)
                const float4* __restrict__ sp =
                    (const float4*)(base + (ch * TT + t) * HWD + y * 28);
                float4 r0 = sp[0], r1 = sp[1], r2 = sp[2], r3 = sp[3];
                float4 r4 = sp[4], r5 = sp[5], r6 = sp[6];
                float* d = pooled + (ch * TT + t) * 49 + y * 7;
                d[0] = 0.25f * (r0.x + r0.y + r3.z + r3.w);
                d[1] = 0.25f * (r0.z + r0.w + r4.x + r4.y);
                d[2] = 0.25f * (r1.x + r1.y + r4.z + r4.w);
                d[3] = 0.25f * (r1.z + r1.w + r5.x + r5.y);
                d[4] = 0.25f * (r2.x + r2.y + r5.z + r5.w);
                d[5] = 0.25f * (r2.z + r2.w + r6.x + r6.y);
                d[6] = 0.25f * (r3.x + r3.y + r6.z + r6.w);
            }
            __syncthreads();

            if (threadIdx.x < CPB_P * 49) {            // 98 column sums
                int ch = threadIdx.x / 49, blk = threadIdx.x - ch * 49;
                const float* pc = pooled + ch * (TT * 49) + blk;
                float s = 0.f;
                #pragma unroll
                for (int t = 0; t < TT; t++) s += pc[t * 49];
                sc[threadIdx.x] = s;
            }
            __syncthreads();

            {
                const int ch = threadIdx.x >> 7;
                const int t  = (threadIdx.x >> 3) & 15;
                const int g  = threadIdx.x & 7;
                const float* pr = pooled + ch * (TT * 49) + t * 49;
                const float* sr = sc + ch * 49;
                float acc = 0.f;
                #pragma unroll
                for (int blk = g; blk < 49; blk += 8)
                    acc += pr[blk] * sr[blk];
                acc += __shfl_xor_sync(0xffffffffu, acc, 4);
                acc += __shfl_xor_sync(0xffffffffu, acc, 2);
                acc += __shfl_xor_sync(0xffffffffu, acc, 1);
                if (g == 0) {
                    int bc = bc0 + ch;
                    g_partial[(b * TT + t) * CC + (bc & (CC - 1))] = acc;
                }
            }
            __syncthreads();

            // per-batch completion; last arrival (of 256) does the select
            if (threadIdx.x == 0) {
                __threadfence();
                unsigned pc = atomicAdd(&g_pcnt[b], 1u);
                sm_sel = ((pc & 255u) == 255u);
            }
            __syncthreads();
            if (sm_sel) {
                __threadfence();                       // see all batch partials
                {
                    int t = threadIdx.x >> 4, g = threadIdx.x & 15;
                    const float* __restrict__ pp = g_partial + (b * TT + t) * CC;
                    float s = 0.f;
                    #pragma unroll
                    for (int j = 0; j < CC / 16; j++) s += __ldcg(&pp[g + 16 * j]);
                    s += __shfl_xor_sync(0xffffffffu, s, 8);
                    s += __shfl_xor_sync(0xffffffffu, s, 4);
                    s += __shfl_xor_sync(0xffffffffu, s, 2);
                    s += __shfl_xor_sync(0xffffffffu, s, 1);
                    if (g == 0)
                        v[t] = s * (1.0f / (float)(CC * TT)) + ((t & 1) == 0 ? 1.0f : 0.0f);
                }
                __syncthreads();
                if (threadIdx.x < TT) {                // jax top_k tie semantics
                    const int i = threadIdx.x;
                    const float mv = v[i];
                    int ra = 0, rd = 0;
                    #pragma unroll
                    for (int j = 0; j < TT; j++) {
                        float vj = v[j];
                        ra += (vj > mv) || (vj == mv && j < i);
                        rd += (vj < mv) || (vj == mv && j < i);
                    }
                    fa[i] = (ra < KK);
                    fd[i] = (rd < KK);
                }
                __syncthreads();
                if (threadIdx.x < TT) {
                    const int i = threadIdx.x;
                    int pa = 0, pd = 0;
                    for (int j = 0; j < i; j++) { pa += fa[j]; pd += fd[j]; }
                    g_dest[b * TT + i] = fa[i] ? pa : (KK + pd);  // exactly one set
                }
            }
            __syncthreads();                           // smem reuse
        }

        // =============== grid barrier (modulo counter) ===================
        if (threadIdx.x == 0) {
            __threadfence();                           // publish g_dest
            atomicAdd(&g_bar[chunk], 1u);
            while ((*(volatile unsigned*)&g_bar[chunk]) % N != 0u)
                __nanosleep(64);
            __threadfence();
        }
        __syncthreads();

        // ============ gather phase: work-stealing, 2-slab units ==========
        for (;;) {
            if (threadIdx.x == 0)
                sm_u = atomicAdd(&g_tkg[chunk], 1u) % MODG;
            __syncthreads();
            const unsigned u = sm_u;
            if (u >= GATH_UNITS) break;

            const int b  = b0 + (int)(u >> 8);         // 256 units per batch
            const int c0 = (int)(u & 255) << 1;        // 2 channels per unit

            if (threadIdx.x < TT)
                dst_slot[threadIdx.x] = __ldcg(&g_dest[b * TT + threadIdx.x]);
            __syncthreads();

            for (int i = threadIdx.x; i < CPB_G * TT * 49; i += 256) {
                int cl  = i / 784;
                int r   = i - cl * 784;
                int t   = r / 49;
                int hw4 = r - t * 49;
                float4 val = __ldcs(&src4[((size_t)(b * CC + c0 + cl) * TT + t) * 49 + hw4]);
                int s = dst_slot[t];
                unsigned half = (unsigned)s >> 3;
                unsigned j = (unsigned)s & (KK - 1);
                size_t o = (size_t)half * (BB * CC * KK * 49)
                         + ((size_t)(b * CC + c0 + cl) * KK + j) * 49 + hw4;
                __stcs(&out4[o], val);
            }
            __syncthreads();                           // dst_slot/sm_u reuse
        }
    }
}

// ---------------------------------------------------------------------------
extern "C" void kernel_launch(void* const* d_in, const int* in_sizes, int n_in,
                              void* d_out, int out_size) {
    const float* x = (const float*)d_in[0];
    float* out = (float*)d_out;

    // Host-side sizing runs at capture time only; deterministic per device.
    int dev = 0;
    cudaGetDevice(&dev);
    int nsm = 0;
    cudaDeviceGetAttribute(&nsm, cudaDevAttrMultiProcessorCount, dev);
    int bpm = 0;
    cudaOccupancyMaxActiveBlocksPerMultiprocessor(&bpm, k_fused, 256, 0);
    if (bpm < 1) bpm = 1;
    int grid = nsm * bpm;                     // single wave guaranteed
    if (grid > GRID_TGT) grid = GRID_TGT;

    k_fused<<<grid, 256>>>(x, out);
}